// round 1
// baseline (speedup 1.0000x reference)
#include <cuda_runtime.h>

// Causal SDPA, B=4 H=16 S=2048 D=64, fp32. Flash-attention style, one kernel.
// Packed f32x2 FFMA throughout (full-rate fp32 on sm_103a; scalar FFMA-3reg is half rate).

namespace {

constexpr int Sc = 2048;
constexpr int Dc = 64;
constexpr int BM = 64;   // Q rows per CTA
constexpr int BN = 64;   // KV rows per tile
constexpr int NT = 128;  // threads per CTA

typedef unsigned long long u64;

__device__ __forceinline__ u64 pack2(float lo, float hi) {
  u64 r;
  asm("mov.b64 %0, {%1, %2};" : "=l"(r) : "f"(lo), "f"(hi));
  return r;
}
__device__ __forceinline__ void unpack2(u64 v, float& lo, float& hi) {
  asm("mov.b64 {%0, %1}, %2;" : "=f"(lo), "=f"(hi) : "l"(v));
}
__device__ __forceinline__ void fma2(u64& d, u64 a, u64 b) {
  asm("fma.rn.f32x2 %0, %1, %2, %0;" : "+l"(d) : "l"(a), "l"(b));
}
__device__ __forceinline__ u64 mul2(u64 a, u64 b) {
  u64 d;
  asm("mul.rn.f32x2 %0, %1, %2;" : "=l"(d) : "l"(a), "l"(b));
  return d;
}

__global__ __launch_bounds__(NT, 1) void fa_fwd(
    const float* __restrict__ Qg, const float* __restrict__ Kg,
    const float* __restrict__ Vg, float* __restrict__ Og) {
  extern __shared__ float smem[];
  float* Qs = smem;          // [64][64] transposed: Qs[d*64+m], prescaled by 0.125
  float* Ks = smem + 4096;   // [64][64] transposed: Ks[d*64+n]; reused as P^T[n*64+m]
  float* Vs = smem + 8192;   // [64][64] natural:    Vs[n*64+d]

  const int tid = threadIdx.x;
  const int tm4 = (tid >> 3) << 2;  // 4 query rows starting here
  const int tn8 = (tid & 7) << 3;   // 8 kv cols / 8 d cols starting here
  const int qt = (int)(gridDim.x - 1) - (int)blockIdx.x;  // big (causal-long) tiles first
  const int q0 = qt * BM;
  const size_t bh = blockIdx.y;
  const float* Qp = Qg + (bh * Sc + q0) * (size_t)Dc;
  const float* Kp0 = Kg + bh * (size_t)Sc * Dc;
  const float* Vp0 = Vg + bh * (size_t)Sc * Dc;

  // Load Q tile transposed, fold in softmax scale 1/sqrt(64) = 0.125 (exact).
#pragma unroll
  for (int it = 0; it < 8; ++it) {
    int idx4 = tid + it * NT;   // 0..1023 float4 index into 64x64 tile
    int r = idx4 >> 4;          // q row in tile
    int c = (idx4 & 15) << 2;   // d base
    float4 v = *(const float4*)(Qp + (size_t)r * Dc + c);
    Qs[(c + 0) * 64 + r] = v.x * 0.125f;
    Qs[(c + 1) * 64 + r] = v.y * 0.125f;
    Qs[(c + 2) * 64 + r] = v.z * 0.125f;
    Qs[(c + 3) * 64 + r] = v.w * 0.125f;
  }

  u64 Ob[4][4];  // O accumulator, 4 rows x 8 d-cols (packed pairs)
  float m_[4], l_[4];
#pragma unroll
  for (int i = 0; i < 4; ++i) {
    m_[i] = -1e30f;
    l_[i] = 0.f;
#pragma unroll
    for (int j = 0; j < 4; ++j) Ob[i][j] = 0ull;
  }

  for (int t = 0; t <= qt; ++t) {
    const int n0 = t * BN;
    const float* Kp = Kp0 + (size_t)n0 * Dc;
    const float* Vp = Vp0 + (size_t)n0 * Dc;
#pragma unroll
    for (int it = 0; it < 8; ++it) {
      int idx4 = tid + it * NT;
      int r = idx4 >> 4;
      int c = (idx4 & 15) << 2;
      float4 v = *(const float4*)(Kp + (size_t)r * Dc + c);
      Ks[(c + 0) * 64 + r] = v.x;
      Ks[(c + 1) * 64 + r] = v.y;
      Ks[(c + 2) * 64 + r] = v.z;
      Ks[(c + 3) * 64 + r] = v.w;
      *(float4*)(Vs + idx4 * 4) = *(const float4*)(Vp + idx4 * 4);
    }
    __syncthreads();

    // scores = (Q*0.125) @ K^T  -- contraction over d
    u64 acc[4][4];
#pragma unroll
    for (int i = 0; i < 4; ++i)
#pragma unroll
      for (int j = 0; j < 4; ++j) acc[i][j] = 0ull;

#pragma unroll 8
    for (int k = 0; k < 64; ++k) {
      float4 q = *(const float4*)(Qs + k * 64 + tm4);
      const ulonglong2* kp = (const ulonglong2*)(Ks + k * 64 + tn8);
      ulonglong2 kA = kp[0];
      ulonglong2 kB = kp[1];
      u64 qq0 = pack2(q.x, q.x), qq1 = pack2(q.y, q.y);
      u64 qq2 = pack2(q.z, q.z), qq3 = pack2(q.w, q.w);
      fma2(acc[0][0], qq0, kA.x); fma2(acc[0][1], qq0, kA.y);
      fma2(acc[0][2], qq0, kB.x); fma2(acc[0][3], qq0, kB.y);
      fma2(acc[1][0], qq1, kA.x); fma2(acc[1][1], qq1, kA.y);
      fma2(acc[1][2], qq1, kB.x); fma2(acc[1][3], qq1, kB.y);
      fma2(acc[2][0], qq2, kA.x); fma2(acc[2][1], qq2, kA.y);
      fma2(acc[2][2], qq2, kB.x); fma2(acc[2][3], qq2, kB.y);
      fma2(acc[3][0], qq3, kA.x); fma2(acc[3][1], qq3, kA.y);
      fma2(acc[3][2], qq3, kB.x); fma2(acc[3][3], qq3, kB.y);
    }

    // online softmax on the 4x8 register tile
    const bool diag = (t == qt);
#pragma unroll
    for (int i = 0; i < 4; ++i) {
      float s[8];
      unpack2(acc[i][0], s[0], s[1]);
      unpack2(acc[i][1], s[2], s[3]);
      unpack2(acc[i][2], s[4], s[5]);
      unpack2(acc[i][3], s[6], s[7]);
      if (diag) {
        int rr = tm4 + i;
#pragma unroll
        for (int j = 0; j < 8; ++j)
          if (tn8 + j > rr) s[j] = -1e30f;  // == ref's -1e7 fill: exp underflows to 0
      }
      float mt = s[0];
#pragma unroll
      for (int j = 1; j < 8; ++j) mt = fmaxf(mt, s[j]);
#pragma unroll
      for (int o = 1; o < 8; o <<= 1)
        mt = fmaxf(mt, __shfl_xor_sync(0xffffffffu, mt, o));
      float mn = fmaxf(m_[i], mt);
      float al = __expf(m_[i] - mn);
      float rs = 0.f;
#pragma unroll
      for (int j = 0; j < 8; ++j) {
        s[j] = __expf(s[j] - mn);
        rs += s[j];
      }
#pragma unroll
      for (int o = 1; o < 8; o <<= 1)
        rs += __shfl_xor_sync(0xffffffffu, rs, o);
      l_[i] = l_[i] * al + rs;
      m_[i] = mn;
      u64 aa = pack2(al, al);
#pragma unroll
      for (int j = 0; j < 4; ++j) {
        Ob[i][j] = mul2(Ob[i][j], aa);
        acc[i][j] = pack2(s[2 * j], s[2 * j + 1]);  // keep p for post-sync store
      }
    }
    __syncthreads();  // everyone done reading Ks before it becomes P^T

    // write P^T into the K buffer: Ps[n*64 + m]
#pragma unroll
    for (int i = 0; i < 4; ++i) {
#pragma unroll
      for (int j = 0; j < 4; ++j) {
        float p0, p1;
        unpack2(acc[i][j], p0, p1);
        Ks[(tn8 + 2 * j + 0) * 64 + tm4 + i] = p0;
        Ks[(tn8 + 2 * j + 1) * 64 + tm4 + i] = p1;
      }
    }
    __syncthreads();

    // O += P @ V  -- contraction over n
#pragma unroll 8
    for (int n = 0; n < 64; ++n) {
      float4 p = *(const float4*)(Ks + n * 64 + tm4);
      const ulonglong2* vp = (const ulonglong2*)(Vs + n * 64 + tn8);
      ulonglong2 vA = vp[0];
      ulonglong2 vB = vp[1];
      u64 pp0 = pack2(p.x, p.x), pp1 = pack2(p.y, p.y);
      u64 pp2 = pack2(p.z, p.z), pp3 = pack2(p.w, p.w);
      fma2(Ob[0][0], pp0, vA.x); fma2(Ob[0][1], pp0, vA.y);
      fma2(Ob[0][2], pp0, vB.x); fma2(Ob[0][3], pp0, vB.y);
      fma2(Ob[1][0], pp1, vA.x); fma2(Ob[1][1], pp1, vA.y);
      fma2(Ob[1][2], pp1, vB.x); fma2(Ob[1][3], pp1, vB.y);
      fma2(Ob[2][0], pp2, vA.x); fma2(Ob[2][1], pp2, vA.y);
      fma2(Ob[2][2], pp2, vB.x); fma2(Ob[2][3], pp2, vB.y);
      fma2(Ob[3][0], pp3, vA.x); fma2(Ob[3][1], pp3, vA.y);
      fma2(Ob[3][2], pp3, vB.x); fma2(Ob[3][3], pp3, vB.y);
    }
    __syncthreads();  // before next-tile loads overwrite Ks/Vs
  }

  // epilogue: normalize and store
  float* Op = Og + (bh * Sc + q0) * (size_t)Dc;
#pragma unroll
  for (int i = 0; i < 4; ++i) {
    float inv = 1.f / l_[i];
    u64 iv = pack2(inv, inv);
    int r = tm4 + i;
#pragma unroll
    for (int j = 0; j < 4; ++j) {
      u64 o = mul2(Ob[i][j], iv);
      *(u64*)(Op + (size_t)r * Dc + tn8 + 2 * j) = o;
    }
  }
}

}  // namespace

extern "C" void kernel_launch(void* const* d_in, const int* in_sizes, int n_in,
                              void* d_out, int out_size) {
  const float* Q = (const float*)d_in[0];
  const float* K = (const float*)d_in[1];
  const float* V = (const float*)d_in[2];
  float* O = (float*)d_out;
  (void)in_sizes; (void)n_in; (void)out_size;

  constexpr int B = 4, H = 16;
  constexpr int smem_bytes = 3 * 64 * 64 * (int)sizeof(float);  // 49152
  // Defensive (49152 == default limit, but make it explicit). Host-side, capture-safe.
  cudaFuncSetAttribute(fa_fwd, cudaFuncAttributeMaxDynamicSharedMemorySize, smem_bytes);

  dim3 grid(Sc / BM, B * H);
  fa_fwd<<<grid, NT, smem_bytes>>>(Q, K, V, O);
}

// round 3
// speedup vs baseline: 1.4438x; 1.4438x over previous
#include <cuda_runtime.h>

// Causal SDPA, B=4 H=16 S=2048 D=64, fp32. Flash-attention, packed f32x2 FFMA.
// R1 fix (re-bench; prior submission hit GPU-broker timeout): 8x8 per-thread
// tiles (2x FMA per LDS), register-block transposes (float4 smem stores, no
// 16-way conflicts), 96KB smem, 2 CTAs/SM.

namespace {

constexpr int Sc = 2048;
constexpr int Dc = 64;
constexpr int BM = 128;  // Q rows per CTA
constexpr int BN = 64;   // KV rows per tile
constexpr int NT = 128;  // threads

typedef unsigned long long u64;

__device__ __forceinline__ u64 pack2(float lo, float hi) {
  u64 r;
  asm("mov.b64 %0, {%1, %2};" : "=l"(r) : "f"(lo), "f"(hi));
  return r;
}
__device__ __forceinline__ void unpack2(u64 v, float& lo, float& hi) {
  asm("mov.b64 {%0, %1}, %2;" : "=f"(lo), "=f"(hi) : "l"(v));
}
__device__ __forceinline__ void fma2(u64& d, u64 a, u64 b) {
  asm("fma.rn.f32x2 %0, %1, %2, %0;" : "+l"(d) : "l"(a), "l"(b));
}
__device__ __forceinline__ u64 mul2(u64 a, u64 b) {
  u64 d;
  asm("mul.rn.f32x2 %0, %1, %2;" : "=l"(d) : "l"(a), "l"(b));
  return d;
}

__global__ __launch_bounds__(NT, 2) void fa_fwd(
    const float* __restrict__ Qg, const float* __restrict__ Kg,
    const float* __restrict__ Vg, float* __restrict__ Og) {
  extern __shared__ float smf[];
  float* Qs = smf;                  // [64][128] d-major, prescaled by 0.125
  float* Ks = smf + 8192;           // [64][64]  d-major
  float* Ps = smf + 8192 + 4096;    // [64][128] P^T: [n][m]
  float* Vs = smf + 8192 + 4096 + 8192;  // [64][64] natural [n][d]

  const int tid = threadIdx.x;
  const int tm8 = (tid >> 3) << 3;  // 8 query rows
  const int tn8 = (tid & 7) << 3;   // 8 kv/d cols
  const int qt = (int)(gridDim.x - 1) - (int)blockIdx.x;  // long tiles first
  const int q0 = qt * BM;
  const size_t bh = blockIdx.y;
  const float* Qp = Qg + (bh * Sc + q0) * (size_t)Dc;
  const float* Kb = Kg + bh * (size_t)Sc * Dc;
  const float* Vb = Vg + bh * (size_t)Sc * Dc;

  // ---- Q: load, 4x4 register transpose, scale by 1/sqrt(64)=0.125, store ----
#pragma unroll
  for (int ii = 0; ii < 4; ++ii) {
    int blk = tid + ii * NT;       // 0..511 -> (mb 0..31, db 0..15)
    int mb = (blk & 31) * 4;
    int db = (blk >> 5) * 4;
    float4 r0 = *(const float4*)(Qp + (size_t)(mb + 0) * Dc + db);
    float4 r1 = *(const float4*)(Qp + (size_t)(mb + 1) * Dc + db);
    float4 r2 = *(const float4*)(Qp + (size_t)(mb + 2) * Dc + db);
    float4 r3 = *(const float4*)(Qp + (size_t)(mb + 3) * Dc + db);
    const float s = 0.125f;
    *(float4*)(Qs + (db + 0) * 128 + mb) = make_float4(r0.x * s, r1.x * s, r2.x * s, r3.x * s);
    *(float4*)(Qs + (db + 1) * 128 + mb) = make_float4(r0.y * s, r1.y * s, r2.y * s, r3.y * s);
    *(float4*)(Qs + (db + 2) * 128 + mb) = make_float4(r0.z * s, r1.z * s, r2.z * s, r3.z * s);
    *(float4*)(Qs + (db + 3) * 128 + mb) = make_float4(r0.w * s, r1.w * s, r2.w * s, r3.w * s);
  }

  u64 Ob[8][4];
  float m_[8], l_[8];
#pragma unroll
  for (int i = 0; i < 8; ++i) {
    m_[i] = -1e30f;
    l_[i] = 0.f;
#pragma unroll
    for (int j = 0; j < 4; ++j) Ob[i][j] = 0ull;
  }

  const int ntiles = 2 * qt + 2;
  for (int t = 0; t < ntiles; ++t) {
    const int n0 = t * BN;
    const float* Kp = Kb + (size_t)n0 * Dc;
    const float* Vp = Vb + (size_t)n0 * Dc;

    // K: load + 4x4 register transpose -> Ks[d][n] (float4 stores, ~2-way max)
#pragma unroll
    for (int ii = 0; ii < 2; ++ii) {
      int blk = tid + ii * NT;     // 0..255 -> (nb 0..15, db 0..15)
      int nb = (blk & 15) * 4;
      int db = (blk >> 4) * 4;
      float4 r0 = *(const float4*)(Kp + (size_t)(nb + 0) * Dc + db);
      float4 r1 = *(const float4*)(Kp + (size_t)(nb + 1) * Dc + db);
      float4 r2 = *(const float4*)(Kp + (size_t)(nb + 2) * Dc + db);
      float4 r3 = *(const float4*)(Kp + (size_t)(nb + 3) * Dc + db);
      *(float4*)(Ks + (db + 0) * 64 + nb) = make_float4(r0.x, r1.x, r2.x, r3.x);
      *(float4*)(Ks + (db + 1) * 64 + nb) = make_float4(r0.y, r1.y, r2.y, r3.y);
      *(float4*)(Ks + (db + 2) * 64 + nb) = make_float4(r0.z, r1.z, r2.z, r3.z);
      *(float4*)(Ks + (db + 3) * 64 + nb) = make_float4(r0.w, r1.w, r2.w, r3.w);
    }
    // V: straight copy, coalesced + conflict-free
#pragma unroll
    for (int ii = 0; ii < 8; ++ii) {
      int i4 = tid + ii * NT;
      *(float4*)(Vs + i4 * 4) = *(const float4*)(Vp + (size_t)i4 * 4);
    }
    __syncthreads();

    // ---- S = (Q*0.125) @ K^T : contraction over d ----
    u64 acc[8][4];
#pragma unroll
    for (int i = 0; i < 8; ++i)
#pragma unroll
      for (int j = 0; j < 4; ++j) acc[i][j] = 0ull;

#pragma unroll 4
    for (int k = 0; k < 64; ++k) {
      float4 qa = *(const float4*)(Qs + k * 128 + tm8);
      float4 qb = *(const float4*)(Qs + k * 128 + tm8 + 4);
      ulonglong2 kA = *(const ulonglong2*)(Ks + k * 64 + tn8);
      ulonglong2 kB = *(const ulonglong2*)(Ks + k * 64 + tn8 + 4);
      float qv[8] = {qa.x, qa.y, qa.z, qa.w, qb.x, qb.y, qb.z, qb.w};
#pragma unroll
      for (int i = 0; i < 8; ++i) {
        u64 qq = pack2(qv[i], qv[i]);
        fma2(acc[i][0], qq, kA.x);
        fma2(acc[i][1], qq, kA.y);
        fma2(acc[i][2], qq, kB.x);
        fma2(acc[i][3], qq, kB.y);
      }
    }

    // ---- online softmax (8 rows), p kept in regs ----
    const bool masked = (n0 + BN - 1 > q0);  // uniform across CTA
    float ps[8][8];
#pragma unroll
    for (int i = 0; i < 8; ++i) {
      float s[8];
      unpack2(acc[i][0], s[0], s[1]);
      unpack2(acc[i][1], s[2], s[3]);
      unpack2(acc[i][2], s[4], s[5]);
      unpack2(acc[i][3], s[6], s[7]);
      if (masked) {
        int qr = q0 + tm8 + i;
#pragma unroll
        for (int j = 0; j < 8; ++j)
          if (n0 + tn8 + j > qr) s[j] = -1e30f;
      }
      float mt = s[0];
#pragma unroll
      for (int j = 1; j < 8; ++j) mt = fmaxf(mt, s[j]);
#pragma unroll
      for (int o = 1; o < 8; o <<= 1)
        mt = fmaxf(mt, __shfl_xor_sync(0xffffffffu, mt, o));
      float mn = fmaxf(m_[i], mt);
      float al = __expf(m_[i] - mn);
      float rs = 0.f;
#pragma unroll
      for (int j = 0; j < 8; ++j) {
        float e = __expf(s[j] - mn);
        ps[i][j] = e;
        rs += e;
      }
#pragma unroll
      for (int o = 1; o < 8; o <<= 1)
        rs += __shfl_xor_sync(0xffffffffu, rs, o);
      l_[i] = l_[i] * al + rs;
      m_[i] = mn;
      u64 aa = pack2(al, al);
#pragma unroll
      for (int j = 0; j < 4; ++j) Ob[i][j] = mul2(Ob[i][j], aa);
    }

    // ---- store P^T column-wise as float4: Ps[n][m] ----
#pragma unroll
    for (int j = 0; j < 8; ++j) {
      *(float4*)(Ps + (tn8 + j) * 128 + tm8) =
          make_float4(ps[0][j], ps[1][j], ps[2][j], ps[3][j]);
      *(float4*)(Ps + (tn8 + j) * 128 + tm8 + 4) =
          make_float4(ps[4][j], ps[5][j], ps[6][j], ps[7][j]);
    }
    __syncthreads();

    // ---- O += P @ V : contraction over n ----
#pragma unroll 4
    for (int n = 0; n < 64; ++n) {
      float4 pa = *(const float4*)(Ps + n * 128 + tm8);
      float4 pb = *(const float4*)(Ps + n * 128 + tm8 + 4);
      ulonglong2 vA = *(const ulonglong2*)(Vs + n * 64 + tn8);
      ulonglong2 vB = *(const ulonglong2*)(Vs + n * 64 + tn8 + 4);
      float pv[8] = {pa.x, pa.y, pa.z, pa.w, pb.x, pb.y, pb.z, pb.w};
#pragma unroll
      for (int i = 0; i < 8; ++i) {
        u64 pp = pack2(pv[i], pv[i]);
        fma2(Ob[i][0], pp, vA.x);
        fma2(Ob[i][1], pp, vA.y);
        fma2(Ob[i][2], pp, vB.x);
        fma2(Ob[i][3], pp, vB.y);
      }
    }
    __syncthreads();  // before next tile overwrites Ks/Vs
  }

  // ---- epilogue ----
  float* Op = Og + (bh * Sc + q0) * (size_t)Dc;
#pragma unroll
  for (int i = 0; i < 8; ++i) {
    float inv = 1.f / l_[i];
    u64 iv = pack2(inv, inv);
    float o[8];
    unpack2(mul2(Ob[i][0], iv), o[0], o[1]);
    unpack2(mul2(Ob[i][1], iv), o[2], o[3]);
    unpack2(mul2(Ob[i][2], iv), o[4], o[5]);
    unpack2(mul2(Ob[i][3], iv), o[6], o[7]);
    float* row = Op + (size_t)(tm8 + i) * Dc + tn8;
    *(float4*)(row) = make_float4(o[0], o[1], o[2], o[3]);
    *(float4*)(row + 4) = make_float4(o[4], o[5], o[6], o[7]);
  }
}

}  // namespace

extern "C" void kernel_launch(void* const* d_in, const int* in_sizes, int n_in,
                              void* d_out, int out_size) {
  const float* Q = (const float*)d_in[0];
  const float* K = (const float*)d_in[1];
  const float* V = (const float*)d_in[2];
  float* O = (float*)d_out;
  (void)in_sizes; (void)n_in; (void)out_size;

  constexpr int B = 4, H = 16;
  constexpr int smem_bytes = (8192 + 4096 + 8192 + 4096) * (int)sizeof(float);  // 98304
  cudaFuncSetAttribute(fa_fwd, cudaFuncAttributeMaxDynamicSharedMemorySize, smem_bytes);

  dim3 grid(Sc / BM, B * H);
  fa_fwd<<<grid, NT, smem_bytes>>>(Q, K, V, O);
}

// round 4
// speedup vs baseline: 1.7047x; 1.1807x over previous
#include <cuda_runtime.h>

// Causal SDPA, B=4 H=16 S=2048 D=64, fp32. Flash-attention, packed f32x2 FFMA.
// R3: (1) MUFU bottleneck removed -- log2-domain scores + polynomial exp2 on
// the fma pipe (the R2 kernel was MUFU-bound: 160M EX2 @ 0.5/cyc/SM = 1.08ms).
// (2) split-column thread mapping -> conflict-free Ks/Vs loads.
// (3) XOR-swizzled P^T buffer (8-way -> 4-way stores).

namespace {

constexpr int Sc = 2048;
constexpr int Dc = 64;
constexpr int BM = 128;  // Q rows per CTA
constexpr int BN = 64;   // KV rows per tile
constexpr int NT = 128;  // threads

// Q prescale: (1/sqrt(64)) * log2(e) -> scores are log2-domain
#define QSCALE 0.180336880111120430f
#define MAGICF 12582912.0f  // 1.5 * 2^23

typedef unsigned long long u64;

__device__ __forceinline__ u64 pack2(float lo, float hi) {
  u64 r;
  asm("mov.b64 %0, {%1, %2};" : "=l"(r) : "f"(lo), "f"(hi));
  return r;
}
__device__ __forceinline__ void unpack2(u64 v, float& lo, float& hi) {
  asm("mov.b64 {%0, %1}, %2;" : "=f"(lo), "=f"(hi) : "l"(v));
}
__device__ __forceinline__ void fma2(u64& d, u64 a, u64 b) {
  asm("fma.rn.f32x2 %0, %1, %2, %0;" : "+l"(d) : "l"(a), "l"(b));
}
__device__ __forceinline__ u64 fma2o(u64 a, u64 b, u64 c) {
  u64 d;
  asm("fma.rn.f32x2 %0, %1, %2, %3;" : "=l"(d) : "l"(a), "l"(b), "l"(c));
  return d;
}
__device__ __forceinline__ u64 add2(u64 a, u64 b) {
  u64 d;
  asm("add.rn.f32x2 %0, %1, %2;" : "=l"(d) : "l"(a), "l"(b));
  return d;
}
__device__ __forceinline__ u64 mul2(u64 a, u64 b) {
  u64 d;
  asm("mul.rn.f32x2 %0, %1, %2;" : "=l"(d) : "l"(a), "l"(b));
  return d;
}

// exp2 poly coeffs (Taylor deg-4, rel err ~4e-5 on [-0.5,0.5])
#define EC1 0.6931471805599453f
#define EC2 0.2402265069591007f
#define EC3 0.0555041086648216f
#define EC4 0.0096181291076285f

// scalar exp2 for the alpha correction (d must be <= 0; clamped inside)
__device__ __forceinline__ float exp2s(float d) {
  d = fmaxf(d, -80.0f);
  float t = d + MAGICF;
  float nf = t - MAGICF;
  float f = d - nf;
  float p = EC3 + f * EC4;
  p = EC2 + f * p;
  p = EC1 + f * p;
  p = 1.0f + f * p;
  return __int_as_float(__float_as_int(p) + (__float_as_int(t) << 23));
}

// P^T swizzled float4-slot index: row n (32 float4s wide), m4 in [0,32)
#define PSIDX(n, m4) (((n) << 5) + ((m4) ^ (((n) >> 2) & 7)))

__global__ __launch_bounds__(NT, 2) void fa_fwd(
    const float* __restrict__ Qg, const float* __restrict__ Kg,
    const float* __restrict__ Vg, float* __restrict__ Og) {
  extern __shared__ float smf[];
  float* Qs = smf;                       // [64][128] d-major, prescaled
  float* Ks = smf + 8192;                // [64][64]  d-major
  float* Ps = smf + 8192 + 4096;         // [64][32 float4] swizzled P^T
  float* Vs = smf + 8192 + 4096 + 8192;  // [64][64]  natural [n][d]

  const int tid = threadIdx.x;
  const int ta = tid >> 3;          // 0..15
  const int tb = tid & 7;           // 0..7
  const int tm8 = ta << 3;          // 8 query rows
  const int cA = 4 * tb;            // first col chunk (n or d): cA..cA+3
  const int cB = 32 + 4 * tb;       // second col chunk: cB..cB+3
  const int qt = (int)(gridDim.x - 1) - (int)blockIdx.x;
  const int q0 = qt * BM;
  const size_t bh = blockIdx.y;
  const float* Qp = Qg + (bh * Sc + q0) * (size_t)Dc;
  const float* Kb = Kg + bh * (size_t)Sc * Dc;
  const float* Vb = Vg + bh * (size_t)Sc * Dc;

  // exp2 constant pairs (held in registers)
  const u64 KC4 = pack2(EC4, EC4), KC3 = pack2(EC3, EC3);
  const u64 KC2 = pack2(EC2, EC2), KC1 = pack2(EC1, EC1);
  const u64 KC0 = pack2(1.0f, 1.0f);
  const u64 KMG = pack2(MAGICF, MAGICF), KNMG = pack2(-MAGICF, -MAGICF);
  const u64 KN1 = pack2(-1.0f, -1.0f);

  // packed exp2: inputs clamped <=0, >=-80; returns packed (2^d0, 2^d1)
  auto exp2p = [&](float d0, float d1) -> u64 {
    u64 d2 = pack2(d0, d1);
    u64 t2 = add2(d2, KMG);
    u64 n2 = add2(t2, KNMG);
    u64 f2 = fma2o(n2, KN1, d2);  // f = d - round(d)
    u64 p2 = fma2o(f2, KC4, KC3);
    p2 = fma2o(f2, p2, KC2);
    p2 = fma2o(f2, p2, KC1);
    p2 = fma2o(f2, p2, KC0);
    float tf0, tf1, pf0, pf1;
    unpack2(t2, tf0, tf1);
    unpack2(p2, pf0, pf1);
    int e0 = __float_as_int(pf0) + (__float_as_int(tf0) << 23);
    int e1 = __float_as_int(pf1) + (__float_as_int(tf1) << 23);
    return pack2(__int_as_float(e0), __int_as_float(e1));
  };

  // ---- Q: load, 4x4 register transpose, prescale, store d-major ----
#pragma unroll
  for (int ii = 0; ii < 4; ++ii) {
    int blk = tid + ii * NT;
    int mb = (blk & 31) * 4;
    int db = (blk >> 5) * 4;
    float4 r0 = *(const float4*)(Qp + (size_t)(mb + 0) * Dc + db);
    float4 r1 = *(const float4*)(Qp + (size_t)(mb + 1) * Dc + db);
    float4 r2 = *(const float4*)(Qp + (size_t)(mb + 2) * Dc + db);
    float4 r3 = *(const float4*)(Qp + (size_t)(mb + 3) * Dc + db);
    const float s = QSCALE;
    *(float4*)(Qs + (db + 0) * 128 + mb) = make_float4(r0.x * s, r1.x * s, r2.x * s, r3.x * s);
    *(float4*)(Qs + (db + 1) * 128 + mb) = make_float4(r0.y * s, r1.y * s, r2.y * s, r3.y * s);
    *(float4*)(Qs + (db + 2) * 128 + mb) = make_float4(r0.z * s, r1.z * s, r2.z * s, r3.z * s);
    *(float4*)(Qs + (db + 3) * 128 + mb) = make_float4(r0.w * s, r1.w * s, r2.w * s, r3.w * s);
  }

  u64 Ob[8][4];
  float m_[8], l_[8];
#pragma unroll
  for (int i = 0; i < 8; ++i) {
    m_[i] = -1e30f;
    l_[i] = 0.f;
#pragma unroll
    for (int j = 0; j < 4; ++j) Ob[i][j] = 0ull;
  }

  const int ntiles = 2 * qt + 2;
  for (int t = 0; t < ntiles; ++t) {
    const int n0 = t * BN;
    const float* Kp = Kb + (size_t)n0 * Dc;
    const float* Vp = Vb + (size_t)n0 * Dc;

    // K: load + 4x4 register transpose -> Ks[d][n]
#pragma unroll
    for (int ii = 0; ii < 2; ++ii) {
      int blk = tid + ii * NT;
      int nb = (blk & 15) * 4;
      int db = (blk >> 4) * 4;
      float4 r0 = *(const float4*)(Kp + (size_t)(nb + 0) * Dc + db);
      float4 r1 = *(const float4*)(Kp + (size_t)(nb + 1) * Dc + db);
      float4 r2 = *(const float4*)(Kp + (size_t)(nb + 2) * Dc + db);
      float4 r3 = *(const float4*)(Kp + (size_t)(nb + 3) * Dc + db);
      *(float4*)(Ks + (db + 0) * 64 + nb) = make_float4(r0.x, r1.x, r2.x, r3.x);
      *(float4*)(Ks + (db + 1) * 64 + nb) = make_float4(r0.y, r1.y, r2.y, r3.y);
      *(float4*)(Ks + (db + 2) * 64 + nb) = make_float4(r0.z, r1.z, r2.z, r3.z);
      *(float4*)(Ks + (db + 3) * 64 + nb) = make_float4(r0.w, r1.w, r2.w, r3.w);
    }
    // V: straight copy
#pragma unroll
    for (int ii = 0; ii < 8; ++ii) {
      int i4 = tid + ii * NT;
      *(float4*)(Vs + i4 * 4) = *(const float4*)(Vp + (size_t)i4 * 4);
    }
    __syncthreads();

    // ---- S = Q @ K^T (log2-domain), cols {cA..cA+3, cB..cB+3} ----
    u64 acc[8][4];
#pragma unroll
    for (int i = 0; i < 8; ++i)
#pragma unroll
      for (int j = 0; j < 4; ++j) acc[i][j] = 0ull;

#pragma unroll 4
    for (int k = 0; k < 64; ++k) {
      float4 qa = *(const float4*)(Qs + k * 128 + tm8);
      float4 qb = *(const float4*)(Qs + k * 128 + tm8 + 4);
      ulonglong2 kA = *(const ulonglong2*)(Ks + k * 64 + cA);
      ulonglong2 kB = *(const ulonglong2*)(Ks + k * 64 + cB);
      float qv[8] = {qa.x, qa.y, qa.z, qa.w, qb.x, qb.y, qb.z, qb.w};
#pragma unroll
      for (int i = 0; i < 8; ++i) {
        u64 qq = pack2(qv[i], qv[i]);
        fma2(acc[i][0], qq, kA.x);
        fma2(acc[i][1], qq, kA.y);
        fma2(acc[i][2], qq, kB.x);
        fma2(acc[i][3], qq, kB.y);
      }
    }

    // ---- online softmax (log2 domain, polynomial exp2) ----
    const bool masked = (n0 + BN - 1 > q0);
    float ps[8][8];
#pragma unroll
    for (int i = 0; i < 8; ++i) {
      float s[8];
      unpack2(acc[i][0], s[0], s[1]);
      unpack2(acc[i][1], s[2], s[3]);
      unpack2(acc[i][2], s[4], s[5]);
      unpack2(acc[i][3], s[6], s[7]);
      if (masked) {
        int qr = q0 + tm8 + i;
#pragma unroll
        for (int j = 0; j < 8; ++j) {
          int ncol = n0 + ((j < 4) ? (cA + j) : (cB + j - 4));
          if (ncol > qr) s[j] = -1e30f;
        }
      }
      float mt = s[0];
#pragma unroll
      for (int j = 1; j < 8; ++j) mt = fmaxf(mt, s[j]);
#pragma unroll
      for (int o = 1; o < 8; o <<= 1)
        mt = fmaxf(mt, __shfl_xor_sync(0xffffffffu, mt, o));
      float mn = fmaxf(m_[i], mt);
      float al = exp2s(m_[i] - mn);
      float rs = 0.f;
#pragma unroll
      for (int jp = 0; jp < 4; ++jp) {
        float d0 = fmaxf(s[2 * jp] - mn, -80.f);
        float d1 = fmaxf(s[2 * jp + 1] - mn, -80.f);
        u64 e2 = exp2p(d0, d1);
        float e0, e1;
        unpack2(e2, e0, e1);
        ps[i][2 * jp] = e0;
        ps[i][2 * jp + 1] = e1;
        rs += e0 + e1;
      }
#pragma unroll
      for (int o = 1; o < 8; o <<= 1)
        rs += __shfl_xor_sync(0xffffffffu, rs, o);
      l_[i] = l_[i] * al + rs;
      m_[i] = mn;
      u64 aa = pack2(al, al);
#pragma unroll
      for (int j = 0; j < 4; ++j) Ob[i][j] = mul2(Ob[i][j], aa);
    }

    // ---- store P^T into swizzled Ps: rows cA+e and cB+e ----
    const int m4a = 2 * ta;  // first m-chunk float4 slot
#pragma unroll
    for (int e = 0; e < 4; ++e) {
      int n1 = cA + e;
      *(float4*)(Ps + 4 * PSIDX(n1, m4a)) =
          make_float4(ps[0][e], ps[1][e], ps[2][e], ps[3][e]);
      *(float4*)(Ps + 4 * PSIDX(n1, m4a + 1)) =
          make_float4(ps[4][e], ps[5][e], ps[6][e], ps[7][e]);
      int n2 = cB + e;
      *(float4*)(Ps + 4 * PSIDX(n2, m4a)) =
          make_float4(ps[0][4 + e], ps[1][4 + e], ps[2][4 + e], ps[3][4 + e]);
      *(float4*)(Ps + 4 * PSIDX(n2, m4a + 1)) =
          make_float4(ps[4][4 + e], ps[5][4 + e], ps[6][4 + e], ps[7][4 + e]);
    }
    __syncthreads();

    // ---- O += P @ V : contraction over n; d-cols {cA, cB} ----
#pragma unroll 4
    for (int n = 0; n < 64; ++n) {
      float4 pa = *(const float4*)(Ps + 4 * PSIDX(n, m4a));
      float4 pb = *(const float4*)(Ps + 4 * PSIDX(n, m4a + 1));
      ulonglong2 vA = *(const ulonglong2*)(Vs + n * 64 + cA);
      ulonglong2 vB = *(const ulonglong2*)(Vs + n * 64 + cB);
      float pv[8] = {pa.x, pa.y, pa.z, pa.w, pb.x, pb.y, pb.z, pb.w};
#pragma unroll
      for (int i = 0; i < 8; ++i) {
        u64 pp = pack2(pv[i], pv[i]);
        fma2(Ob[i][0], pp, vA.x);
        fma2(Ob[i][1], pp, vA.y);
        fma2(Ob[i][2], pp, vB.x);
        fma2(Ob[i][3], pp, vB.y);
      }
    }
    __syncthreads();
  }

  // ---- epilogue ----
  float* Op = Og + (bh * Sc + q0) * (size_t)Dc;
#pragma unroll
  for (int i = 0; i < 8; ++i) {
    float inv = 1.f / l_[i];
    u64 iv = pack2(inv, inv);
    float o[8];
    unpack2(mul2(Ob[i][0], iv), o[0], o[1]);
    unpack2(mul2(Ob[i][1], iv), o[2], o[3]);
    unpack2(mul2(Ob[i][2], iv), o[4], o[5]);
    unpack2(mul2(Ob[i][3], iv), o[6], o[7]);
    float* row = Op + (size_t)(tm8 + i) * Dc;
    *(float4*)(row + cA) = make_float4(o[0], o[1], o[2], o[3]);
    *(float4*)(row + cB) = make_float4(o[4], o[5], o[6], o[7]);
  }
}

}  // namespace

extern "C" void kernel_launch(void* const* d_in, const int* in_sizes, int n_in,
                              void* d_out, int out_size) {
  const float* Q = (const float*)d_in[0];
  const float* K = (const float*)d_in[1];
  const float* V = (const float*)d_in[2];
  float* O = (float*)d_out;
  (void)in_sizes; (void)n_in; (void)out_size;

  constexpr int B = 4, H = 16;
  constexpr int smem_bytes = (8192 + 4096 + 8192 + 4096) * (int)sizeof(float);  // 98304
  cudaFuncSetAttribute(fa_fwd, cudaFuncAttributeMaxDynamicSharedMemorySize, smem_bytes);

  dim3 grid(Sc / BM, B * H);
  fa_fwd<<<grid, NT, smem_bytes>>>(Q, K, V, O);
}

// round 9
// speedup vs baseline: 4.9213x; 2.8870x over previous
#include <cuda_runtime.h>
#include <cuda_fp16.h>

// Causal SDPA, B=4 H=16 S=2048 D=64, fp32.
// R4 (re-bench; prior submissions hit GPU-broker timeouts): tensor-core
// flash attention via mma.sync — tf32 m16n8k8 for Q@K^T, fp16 m16n8k16 for
// P@V. Q in registers, P stays in fragments (no smem round trip), K/V staged
// through smem with conflict-free strides, register double-buffered gmem
// prefetch. Log2-domain softmax + fma-pipe poly exp2.

namespace {

constexpr int Sc = 2048;
constexpr int Dc = 64;
constexpr int BM = 128;  // Q rows per CTA (8 warps x 16 rows)
constexpr int BN = 64;   // KV rows per tile
constexpr int NT = 256;
constexpr int KSTR = 68; // Ks row stride (f32 words)  -> conflict-free b-frag LDS
constexpr int VSTR = 72; // VsT row stride (halves)    -> conflict-free half2 loads

#define QSCALE 0.180336880111120430f  // (1/sqrt(64)) * log2(e)
#define MAGICF 12582912.0f            // 1.5 * 2^23
#define EC1 0.6931471805599453f
#define EC2 0.2402265069591007f
#define EC3 0.0555041086648216f
#define EC4 0.0096181291076285f

typedef unsigned long long u64;
typedef unsigned int u32;

__device__ __forceinline__ u64 pack2(float lo, float hi) {
  u64 r;
  asm("mov.b64 %0, {%1, %2};" : "=l"(r) : "f"(lo), "f"(hi));
  return r;
}
__device__ __forceinline__ void unpack2(u64 v, float& lo, float& hi) {
  asm("mov.b64 {%0, %1}, %2;" : "=f"(lo), "=f"(hi) : "l"(v));
}
__device__ __forceinline__ u64 fma2o(u64 a, u64 b, u64 c) {
  u64 d;
  asm("fma.rn.f32x2 %0, %1, %2, %3;" : "=l"(d) : "l"(a), "l"(b), "l"(c));
  return d;
}
__device__ __forceinline__ u64 add2(u64 a, u64 b) {
  u64 d;
  asm("add.rn.f32x2 %0, %1, %2;" : "=l"(d) : "l"(a), "l"(b));
  return d;
}

// scalar exp2 (input clamped to [-80, 0] inside)
__device__ __forceinline__ float exp2s(float d) {
  d = fmaxf(d, -80.0f);
  float t = d + MAGICF;
  float nf = t - MAGICF;
  float f = d - nf;
  float p = EC3 + f * EC4;
  p = EC2 + f * p;
  p = EC1 + f * p;
  p = 1.0f + f * p;
  return __int_as_float(__float_as_int(p) + (__float_as_int(t) << 23));
}

// packed exp2 of (d0, d1); inputs must already be clamped to [-80, 0]
__device__ __forceinline__ void exp2p2(float d0, float d1, float& e0, float& e1) {
  u64 d2 = pack2(d0, d1);
  u64 t2 = add2(d2, pack2(MAGICF, MAGICF));
  u64 n2 = add2(t2, pack2(-MAGICF, -MAGICF));
  u64 f2 = fma2o(n2, pack2(-1.0f, -1.0f), d2);
  u64 p2 = fma2o(f2, pack2(EC4, EC4), pack2(EC3, EC3));
  p2 = fma2o(f2, p2, pack2(EC2, EC2));
  p2 = fma2o(f2, p2, pack2(EC1, EC1));
  p2 = fma2o(f2, p2, pack2(1.0f, 1.0f));
  float tf0, tf1, pf0, pf1;
  unpack2(t2, tf0, tf1);
  unpack2(p2, pf0, pf1);
  e0 = __int_as_float(__float_as_int(pf0) + (__float_as_int(tf0) << 23));
  e1 = __int_as_float(__float_as_int(pf1) + (__float_as_int(tf1) << 23));
}

__device__ __forceinline__ u32 cvt_tf32(float x) {
  u32 r;
  asm("cvt.rna.tf32.f32 %0, %1;" : "=r"(r) : "f"(x));
  return r;
}
__device__ __forceinline__ u32 h2pack(float lo, float hi) {
  __half2 h = __floats2half2_rn(lo, hi);
  return *reinterpret_cast<u32*>(&h);
}

__device__ __forceinline__ void mma_tf32(float& c0, float& c1, float& c2, float& c3,
                                         u32 a0, u32 a1, u32 a2, u32 a3,
                                         u32 b0, u32 b1) {
  asm("mma.sync.aligned.m16n8k8.row.col.f32.tf32.tf32.f32 "
      "{%0,%1,%2,%3}, {%4,%5,%6,%7}, {%8,%9}, {%0,%1,%2,%3};"
      : "+f"(c0), "+f"(c1), "+f"(c2), "+f"(c3)
      : "r"(a0), "r"(a1), "r"(a2), "r"(a3), "r"(b0), "r"(b1));
}
__device__ __forceinline__ void mma_f16(float& c0, float& c1, float& c2, float& c3,
                                        u32 a0, u32 a1, u32 a2, u32 a3,
                                        u32 b0, u32 b1) {
  asm("mma.sync.aligned.m16n8k16.row.col.f32.f16.f16.f32 "
      "{%0,%1,%2,%3}, {%4,%5,%6,%7}, {%8,%9}, {%0,%1,%2,%3};"
      : "+f"(c0), "+f"(c1), "+f"(c2), "+f"(c3)
      : "r"(a0), "r"(a1), "r"(a2), "r"(a3), "r"(b0), "r"(b1));
}

__global__ __launch_bounds__(NT, 1) void fa_fwd(
    const float* __restrict__ Qg, const float* __restrict__ Kg,
    const float* __restrict__ Vg, float* __restrict__ Og) {
  __shared__ __align__(16) u32 Ks[64 * KSTR];     // tf32 K tile, [n][d], stride 68
  __shared__ __align__(16) __half VsT[64 * VSTR]; // fp16 V^T tile, [d][n], stride 72

  const int tid = threadIdx.x;
  const int w = tid >> 5;       // warp 0..7, rows 16w..16w+15
  const int lane = tid & 31;
  const int g = lane >> 2;      // 0..7
  const int tq = lane & 3;      // 0..3
  const int qt = (int)(gridDim.x - 1) - (int)blockIdx.x;  // long CTAs first
  const int q0 = qt * BM;
  const size_t bh = blockIdx.y;
  const float* Kb = Kg + bh * (size_t)(Sc * Dc);
  const float* Vb = Vg + bh * (size_t)(Sc * Dc);

  // staging maps
  const int kr = tid >> 4;            // K: row (+16*ii), col kc4
  const int kc4 = (tid & 15) << 2;
  const int vnb = (tid & 15) << 2;    // V: 4x4 block transpose
  const int vdb = (tid >> 4) << 2;

  const int ntiles = 2 * qt + 2;

  // ---- prefetch tile 0 into registers ----
  float4 kp[4], vp[4];
#pragma unroll
  for (int ii = 0; ii < 4; ++ii)
    kp[ii] = *(const float4*)(Kb + (size_t)(kr + 16 * ii) * Dc + kc4);
#pragma unroll
  for (int i = 0; i < 4; ++i)
    vp[i] = *(const float4*)(Vb + (size_t)(vnb + i) * Dc + vdb);

  // ---- Q fragments (tf32, prescaled into log2 domain), registers only ----
  u32 qf[8][4];
  {
    const float* Qw = Qg + (bh * Sc + q0 + 16 * w) * (size_t)Dc;
#pragma unroll
    for (int s = 0; s < 8; ++s) {
      int c = 8 * s + tq;
      qf[s][0] = cvt_tf32(Qw[(size_t)g * Dc + c] * QSCALE);
      qf[s][1] = cvt_tf32(Qw[(size_t)(g + 8) * Dc + c] * QSCALE);
      qf[s][2] = cvt_tf32(Qw[(size_t)g * Dc + c + 4] * QSCALE);
      qf[s][3] = cvt_tf32(Qw[(size_t)(g + 8) * Dc + c + 4] * QSCALE);
    }
  }
  const int r0 = q0 + 16 * w + g;  // this thread's two rows: r0, r0+8

  float O[8][4];
#pragma unroll
  for (int dt = 0; dt < 8; ++dt)
#pragma unroll
    for (int c = 0; c < 4; ++c) O[dt][c] = 0.f;
  float m0 = -1e30f, m1 = -1e30f, l0 = 0.f, l1 = 0.f;

  for (int t = 0; t < ntiles; ++t) {
    // ---- store staged tile t into smem ----
#pragma unroll
    for (int ii = 0; ii < 4; ++ii) {
      uint4 kv;
      kv.x = cvt_tf32(kp[ii].x);
      kv.y = cvt_tf32(kp[ii].y);
      kv.z = cvt_tf32(kp[ii].z);
      kv.w = cvt_tf32(kp[ii].w);
      *reinterpret_cast<uint4*>(Ks + (kr + 16 * ii) * KSTR + kc4) = kv;
    }
#pragma unroll
    for (int j = 0; j < 4; ++j) {
      // VsT[vdb+j][vnb..vnb+3] = V[n0+vnb+0..3][vdb+j]
      float e0 = (&vp[0].x)[j], e1 = (&vp[1].x)[j];
      float e2 = (&vp[2].x)[j], e3 = (&vp[3].x)[j];
      uint2 pr;
      pr.x = h2pack(e0, e1);
      pr.y = h2pack(e2, e3);
      *reinterpret_cast<uint2*>(&VsT[(vdb + j) * VSTR + vnb]) = pr;
    }
    __syncthreads();

    const int n0 = t * BN;

    // ---- prefetch tile t+1 (latency overlapped with MMAs below) ----
    if (t + 1 < ntiles) {
      const int nn = (t + 1) * BN;
#pragma unroll
      for (int ii = 0; ii < 4; ++ii)
        kp[ii] = *(const float4*)(Kb + (size_t)(nn + kr + 16 * ii) * Dc + kc4);
#pragma unroll
      for (int i = 0; i < 4; ++i)
        vp[i] = *(const float4*)(Vb + (size_t)(nn + vnb + i) * Dc + vdb);
    }

    // ---- S = Q @ K^T (tf32 tensor MMAs) ----
    float acc[8][4];
#pragma unroll
    for (int j = 0; j < 8; ++j)
#pragma unroll
      for (int c = 0; c < 4; ++c) acc[j][c] = 0.f;

#pragma unroll
    for (int s = 0; s < 8; ++s) {
#pragma unroll
      for (int j = 0; j < 8; ++j) {
        const u32* kb_ = Ks + (8 * j + g) * KSTR + 8 * s + tq;
        mma_tf32(acc[j][0], acc[j][1], acc[j][2], acc[j][3],
                 qf[s][0], qf[s][1], qf[s][2], qf[s][3], kb_[0], kb_[4]);
      }
    }

    // ---- online softmax on fragments (log2 domain) ----
    if (n0 + BN - 1 > q0) {  // tile touches the diagonal
#pragma unroll
      for (int j = 0; j < 8; ++j) {
        int col = n0 + 8 * j + 2 * tq;
        if (col > r0) acc[j][0] = -1e30f;
        if (col + 1 > r0) acc[j][1] = -1e30f;
        if (col > r0 + 8) acc[j][2] = -1e30f;
        if (col + 1 > r0 + 8) acc[j][3] = -1e30f;
      }
    }
    float mt0 = acc[0][0], mt1 = acc[0][2];
#pragma unroll
    for (int j = 0; j < 8; ++j) {
      mt0 = fmaxf(mt0, fmaxf(acc[j][0], acc[j][1]));
      mt1 = fmaxf(mt1, fmaxf(acc[j][2], acc[j][3]));
    }
    mt0 = fmaxf(mt0, __shfl_xor_sync(0xffffffffu, mt0, 1));
    mt0 = fmaxf(mt0, __shfl_xor_sync(0xffffffffu, mt0, 2));
    mt1 = fmaxf(mt1, __shfl_xor_sync(0xffffffffu, mt1, 1));
    mt1 = fmaxf(mt1, __shfl_xor_sync(0xffffffffu, mt1, 2));
    const float mn0 = fmaxf(m0, mt0), mn1 = fmaxf(m1, mt1);
    const float al0 = exp2s(m0 - mn0), al1 = exp2s(m1 - mn1);
    m0 = mn0;
    m1 = mn1;

    float rs0 = 0.f, rs1 = 0.f;
    u32 h2lo[8], h2hi[8];  // fp16 P fragments
#pragma unroll
    for (int j = 0; j < 8; ++j) {
      float e0, e1, e2, e3;
      exp2p2(fmaxf(acc[j][0] - mn0, -80.f), fmaxf(acc[j][1] - mn0, -80.f), e0, e1);
      exp2p2(fmaxf(acc[j][2] - mn1, -80.f), fmaxf(acc[j][3] - mn1, -80.f), e2, e3);
      rs0 += e0 + e1;
      rs1 += e2 + e3;
      h2lo[j] = h2pack(e0, e1);
      h2hi[j] = h2pack(e2, e3);
    }
    rs0 += __shfl_xor_sync(0xffffffffu, rs0, 1);
    rs0 += __shfl_xor_sync(0xffffffffu, rs0, 2);
    rs1 += __shfl_xor_sync(0xffffffffu, rs1, 1);
    rs1 += __shfl_xor_sync(0xffffffffu, rs1, 2);
    l0 = l0 * al0 + rs0;
    l1 = l1 * al1 + rs1;
#pragma unroll
    for (int dt = 0; dt < 8; ++dt) {
      O[dt][0] *= al0;
      O[dt][1] *= al0;
      O[dt][2] *= al1;
      O[dt][3] *= al1;
    }

    // ---- O += P @ V (fp16 tensor MMAs, V^T in smem) ----
#pragma unroll
    for (int u = 0; u < 4; ++u) {
#pragma unroll
      for (int dt = 0; dt < 8; ++dt) {
        const __half* vb_ = VsT + (8 * dt + g) * VSTR + 16 * u + 2 * tq;
        u32 b0 = *reinterpret_cast<const u32*>(vb_);
        u32 b1 = *reinterpret_cast<const u32*>(vb_ + 8);
        mma_f16(O[dt][0], O[dt][1], O[dt][2], O[dt][3],
                h2lo[2 * u], h2hi[2 * u], h2lo[2 * u + 1], h2hi[2 * u + 1], b0, b1);
      }
    }
    __syncthreads();  // before next tile's smem stores
  }

  // ---- epilogue: normalize and store ----
  const float inv0 = 1.f / l0, inv1 = 1.f / l1;
  float* Ow = Og + (bh * Sc + q0 + 16 * w) * (size_t)Dc;
#pragma unroll
  for (int dt = 0; dt < 8; ++dt) {
    int c = 8 * dt + 2 * tq;
    *reinterpret_cast<float2*>(Ow + (size_t)g * Dc + c) =
        make_float2(O[dt][0] * inv0, O[dt][1] * inv0);
    *reinterpret_cast<float2*>(Ow + (size_t)(g + 8) * Dc + c) =
        make_float2(O[dt][2] * inv1, O[dt][3] * inv1);
  }
}

}  // namespace

extern "C" void kernel_launch(void* const* d_in, const int* in_sizes, int n_in,
                              void* d_out, int out_size) {
  const float* Q = (const float*)d_in[0];
  const float* K = (const float*)d_in[1];
  const float* V = (const float*)d_in[2];
  float* O = (float*)d_out;
  (void)in_sizes; (void)n_in; (void)out_size;

  constexpr int B = 4, H = 16;
  dim3 grid(Sc / BM, B * H);
  fa_fwd<<<grid, NT>>>(Q, K, V, O);
}

// round 11
// speedup vs baseline: 5.2834x; 1.0736x over previous
#include <cuda_runtime.h>
#include <cuda_fp16.h>

// Causal SDPA, B=4 H=16 S=2048 D=64, fp32.
// R9 (re-bench; prior submission hit GPU-broker timeout): tensor-core flash
// attention (tf32 QK, fp16 PV) with PERMUTED smem layouts so B-fragments
// load as LDS.128 blocks:
//   K:  col c at row*80 + 20*(c%4) + c/4   -> 4x LDS.128 per j (was 16 LDS.32)
//   Vt: u32 i at row*48 + 12*((i%4)^(r&3)) + i/4 -> 2x LDS.128 per dt (was 8)
// Both conflict-free for quarter-warp 128-bit phases. Q in registers, P in
// fragments, register-prefetched gmem, log2-domain softmax + poly exp2.

namespace {

constexpr int Sc = 2048;
constexpr int Dc = 64;
constexpr int BM = 128;  // Q rows per CTA (8 warps x 16 rows)
constexpr int BN = 64;   // KV rows per tile
constexpr int NT = 256;
constexpr int KROW = 80; // permuted K row stride (u32)
constexpr int VROW = 48; // permuted V^T row stride (u32)

#define QSCALE 0.180336880111120430f  // (1/sqrt(64)) * log2(e)
#define MAGICF 12582912.0f            // 1.5 * 2^23
#define EC1 0.6931471805599453f
#define EC2 0.2402265069591007f
#define EC3 0.0555041086648216f
#define EC4 0.0096181291076285f

typedef unsigned long long u64;
typedef unsigned int u32;

__device__ __forceinline__ u64 pack2(float lo, float hi) {
  u64 r;
  asm("mov.b64 %0, {%1, %2};" : "=l"(r) : "f"(lo), "f"(hi));
  return r;
}
__device__ __forceinline__ void unpack2(u64 v, float& lo, float& hi) {
  asm("mov.b64 {%0, %1}, %2;" : "=f"(lo), "=f"(hi) : "l"(v));
}
__device__ __forceinline__ u64 fma2o(u64 a, u64 b, u64 c) {
  u64 d;
  asm("fma.rn.f32x2 %0, %1, %2, %3;" : "=l"(d) : "l"(a), "l"(b), "l"(c));
  return d;
}
__device__ __forceinline__ u64 add2(u64 a, u64 b) {
  u64 d;
  asm("add.rn.f32x2 %0, %1, %2;" : "=l"(d) : "l"(a), "l"(b));
  return d;
}

// scalar exp2 (input clamped to [-80, 0] inside)
__device__ __forceinline__ float exp2s(float d) {
  d = fmaxf(d, -80.0f);
  float t = d + MAGICF;
  float nf = t - MAGICF;
  float f = d - nf;
  float p = EC3 + f * EC4;
  p = EC2 + f * p;
  p = EC1 + f * p;
  p = 1.0f + f * p;
  return __int_as_float(__float_as_int(p) + (__float_as_int(t) << 23));
}

// packed exp2 of (d0, d1); inputs must already be clamped to [-80, 0]
__device__ __forceinline__ void exp2p2(float d0, float d1, float& e0, float& e1) {
  u64 d2 = pack2(d0, d1);
  u64 t2 = add2(d2, pack2(MAGICF, MAGICF));
  u64 n2 = add2(t2, pack2(-MAGICF, -MAGICF));
  u64 f2 = fma2o(n2, pack2(-1.0f, -1.0f), d2);
  u64 p2 = fma2o(f2, pack2(EC4, EC4), pack2(EC3, EC3));
  p2 = fma2o(f2, p2, pack2(EC2, EC2));
  p2 = fma2o(f2, p2, pack2(EC1, EC1));
  p2 = fma2o(f2, p2, pack2(1.0f, 1.0f));
  float tf0, tf1, pf0, pf1;
  unpack2(t2, tf0, tf1);
  unpack2(p2, pf0, pf1);
  e0 = __int_as_float(__float_as_int(pf0) + (__float_as_int(tf0) << 23));
  e1 = __int_as_float(__float_as_int(pf1) + (__float_as_int(tf1) << 23));
}

__device__ __forceinline__ u32 cvt_tf32(float x) {
  u32 r;
  asm("cvt.rna.tf32.f32 %0, %1;" : "=r"(r) : "f"(x));
  return r;
}
__device__ __forceinline__ u32 h2pack(float lo, float hi) {
  __half2 h = __floats2half2_rn(lo, hi);
  return *reinterpret_cast<u32*>(&h);
}

__device__ __forceinline__ void mma_tf32(float& c0, float& c1, float& c2, float& c3,
                                         u32 a0, u32 a1, u32 a2, u32 a3,
                                         u32 b0, u32 b1) {
  asm("mma.sync.aligned.m16n8k8.row.col.f32.tf32.tf32.f32 "
      "{%0,%1,%2,%3}, {%4,%5,%6,%7}, {%8,%9}, {%0,%1,%2,%3};"
      : "+f"(c0), "+f"(c1), "+f"(c2), "+f"(c3)
      : "r"(a0), "r"(a1), "r"(a2), "r"(a3), "r"(b0), "r"(b1));
}
__device__ __forceinline__ void mma_f16(float& c0, float& c1, float& c2, float& c3,
                                        u32 a0, u32 a1, u32 a2, u32 a3,
                                        u32 b0, u32 b1) {
  asm("mma.sync.aligned.m16n8k16.row.col.f32.f16.f16.f32 "
      "{%0,%1,%2,%3}, {%4,%5,%6,%7}, {%8,%9}, {%0,%1,%2,%3};"
      : "+f"(c0), "+f"(c1), "+f"(c2), "+f"(c3)
      : "r"(a0), "r"(a1), "r"(a2), "r"(a3), "r"(b0), "r"(b1));
}

__global__ __launch_bounds__(NT, 1) void fa_fwd(
    const float* __restrict__ Qg, const float* __restrict__ Kg,
    const float* __restrict__ Vg, float* __restrict__ Og) {
  __shared__ __align__(16) u32 KpS[64 * KROW];  // permuted tf32 K   (20 KB)
  __shared__ __align__(16) u32 VpS[64 * VROW];  // permuted fp16 V^T (12 KB)

  const int tid = threadIdx.x;
  const int w = tid >> 5;       // warp 0..7, rows 16w..16w+15
  const int lane = tid & 31;
  const int g = lane >> 2;      // 0..7
  const int tq = lane & 3;      // 0..3
  const int qt = (int)(gridDim.x - 1) - (int)blockIdx.x;  // long CTAs first
  const int q0 = qt * BM;
  const size_t bh = blockIdx.y;
  const float* Kb = Kg + bh * (size_t)(Sc * Dc);
  const float* Vb = Vg + bh * (size_t)(Sc * Dc);

  // staging maps
  const int kr = tid >> 4;            // K: row (+16*ii), cols kc4..kc4+3
  const int kc4 = (tid & 15) << 2;
  const int vnb = (tid & 15) << 2;    // V: rows vnb..+3, cols vdb..+3
  const int vdb = (tid >> 4) << 2;

  // mainloop smem bases (per thread)
  const int kbase0 = KROW * g + 20 * tq;       // + 640*j per column tile
  const int vxor = 12 * (tq ^ (g & 3));        // V block offset

  const int ntiles = 2 * qt + 2;

  // ---- prefetch tile 0 into registers ----
  float4 kp[4], vp[4];
#pragma unroll
  for (int ii = 0; ii < 4; ++ii)
    kp[ii] = *(const float4*)(Kb + (size_t)(kr + 16 * ii) * Dc + kc4);
#pragma unroll
  for (int i = 0; i < 4; ++i)
    vp[i] = *(const float4*)(Vb + (size_t)(vnb + i) * Dc + vdb);

  // ---- Q fragments (tf32, prescaled into log2 domain), registers only ----
  u32 qf[8][4];
  {
    const float* Qw = Qg + (bh * Sc + q0 + 16 * w) * (size_t)Dc;
#pragma unroll
    for (int s = 0; s < 8; ++s) {
      int c = 8 * s + tq;
      qf[s][0] = cvt_tf32(Qw[(size_t)g * Dc + c] * QSCALE);
      qf[s][1] = cvt_tf32(Qw[(size_t)(g + 8) * Dc + c] * QSCALE);
      qf[s][2] = cvt_tf32(Qw[(size_t)g * Dc + c + 4] * QSCALE);
      qf[s][3] = cvt_tf32(Qw[(size_t)(g + 8) * Dc + c + 4] * QSCALE);
    }
  }
  const int r0 = q0 + 16 * w + g;  // this thread's two rows: r0, r0+8

  float O[8][4];
#pragma unroll
  for (int dt = 0; dt < 8; ++dt)
#pragma unroll
    for (int c = 0; c < 4; ++c) O[dt][c] = 0.f;
  float m0 = -1e30f, m1 = -1e30f, l0 = 0.f, l1 = 0.f;

  for (int t = 0; t < ntiles; ++t) {
    // ---- store staged tile t into permuted smem ----
#pragma unroll
    for (int ii = 0; ii < 4; ++ii) {
      int row = kr + 16 * ii;
      int base = KROW * row + (kc4 >> 2);  // + 20*e per col-in-4
      KpS[base + 0]  = cvt_tf32(kp[ii].x);
      KpS[base + 20] = cvt_tf32(kp[ii].y);
      KpS[base + 40] = cvt_tf32(kp[ii].z);
      KpS[base + 60] = cvt_tf32(kp[ii].w);
    }
#pragma unroll
    for (int j = 0; j < 4; ++j) {
      // V^T row r = vdb+j gets half2 pairs from V rows vnb..vnb+3
      int r = vdb + j;
      int x = r & 3;
      int i0 = vnb >> 1;  // even u32 index
      float e0 = (&vp[0].x)[j], e1 = (&vp[1].x)[j];
      float e2 = (&vp[2].x)[j], e3 = (&vp[3].x)[j];
      VpS[VROW * r + 12 * ((i0 & 3) ^ x) + (i0 >> 2)] = h2pack(e0, e1);
      VpS[VROW * r + 12 * (((i0 + 1) & 3) ^ x) + ((i0 + 1) >> 2)] = h2pack(e2, e3);
    }
    __syncthreads();

    const int n0 = t * BN;

    // ---- prefetch tile t+1 (latency overlapped with MMAs below) ----
    if (t + 1 < ntiles) {
      const int nn = (t + 1) * BN;
#pragma unroll
      for (int ii = 0; ii < 4; ++ii)
        kp[ii] = *(const float4*)(Kb + (size_t)(nn + kr + 16 * ii) * Dc + kc4);
#pragma unroll
      for (int i = 0; i < 4; ++i)
        vp[i] = *(const float4*)(Vb + (size_t)(nn + vnb + i) * Dc + vdb);
    }

    // ---- S = Q @ K^T (tf32 tensor MMAs; block-loaded b-frags) ----
    float acc[8][4];
#pragma unroll
    for (int j = 0; j < 8; ++j)
#pragma unroll
      for (int c = 0; c < 4; ++c) acc[j][c] = 0.f;

#pragma unroll
    for (int j = 0; j < 8; ++j) {
      const u32* kb_ = KpS + kbase0 + 640 * j;  // 640 = 8*KROW
      uint4 w0 = *reinterpret_cast<const uint4*>(kb_ + 0);
      uint4 w1 = *reinterpret_cast<const uint4*>(kb_ + 4);
      uint4 w2 = *reinterpret_cast<const uint4*>(kb_ + 8);
      uint4 w3 = *reinterpret_cast<const uint4*>(kb_ + 12);
      u32 kw[16] = {w0.x, w0.y, w0.z, w0.w, w1.x, w1.y, w1.z, w1.w,
                    w2.x, w2.y, w2.z, w2.w, w3.x, w3.y, w3.z, w3.w};
#pragma unroll
      for (int s = 0; s < 8; ++s)
        mma_tf32(acc[j][0], acc[j][1], acc[j][2], acc[j][3],
                 qf[s][0], qf[s][1], qf[s][2], qf[s][3], kw[2 * s], kw[2 * s + 1]);
    }

    // ---- online softmax on fragments (log2 domain) ----
    if (n0 + BN - 1 > q0) {  // tile touches the diagonal
#pragma unroll
      for (int j = 0; j < 8; ++j) {
        int col = n0 + 8 * j + 2 * tq;
        if (col > r0) acc[j][0] = -1e30f;
        if (col + 1 > r0) acc[j][1] = -1e30f;
        if (col > r0 + 8) acc[j][2] = -1e30f;
        if (col + 1 > r0 + 8) acc[j][3] = -1e30f;
      }
    }
    float mt0 = acc[0][0], mt1 = acc[0][2];
#pragma unroll
    for (int j = 0; j < 8; ++j) {
      mt0 = fmaxf(mt0, fmaxf(acc[j][0], acc[j][1]));
      mt1 = fmaxf(mt1, fmaxf(acc[j][2], acc[j][3]));
    }
    mt0 = fmaxf(mt0, __shfl_xor_sync(0xffffffffu, mt0, 1));
    mt0 = fmaxf(mt0, __shfl_xor_sync(0xffffffffu, mt0, 2));
    mt1 = fmaxf(mt1, __shfl_xor_sync(0xffffffffu, mt1, 1));
    mt1 = fmaxf(mt1, __shfl_xor_sync(0xffffffffu, mt1, 2));
    const float mn0 = fmaxf(m0, mt0), mn1 = fmaxf(m1, mt1);
    const float al0 = exp2s(m0 - mn0), al1 = exp2s(m1 - mn1);
    m0 = mn0;
    m1 = mn1;

    float rs0 = 0.f, rs1 = 0.f;
    u32 h2lo[8], h2hi[8];  // fp16 P fragments
#pragma unroll
    for (int j = 0; j < 8; ++j) {
      float e0, e1, e2, e3;
      exp2p2(fmaxf(acc[j][0] - mn0, -80.f), fmaxf(acc[j][1] - mn0, -80.f), e0, e1);
      exp2p2(fmaxf(acc[j][2] - mn1, -80.f), fmaxf(acc[j][3] - mn1, -80.f), e2, e3);
      rs0 += e0 + e1;
      rs1 += e2 + e3;
      h2lo[j] = h2pack(e0, e1);
      h2hi[j] = h2pack(e2, e3);
    }
    rs0 += __shfl_xor_sync(0xffffffffu, rs0, 1);
    rs0 += __shfl_xor_sync(0xffffffffu, rs0, 2);
    rs1 += __shfl_xor_sync(0xffffffffu, rs1, 1);
    rs1 += __shfl_xor_sync(0xffffffffu, rs1, 2);
    l0 = l0 * al0 + rs0;
    l1 = l1 * al1 + rs1;
#pragma unroll
    for (int dt = 0; dt < 8; ++dt) {
      O[dt][0] *= al0;
      O[dt][1] *= al0;
      O[dt][2] *= al1;
      O[dt][3] *= al1;
    }

    // ---- O += P @ V (fp16 tensor MMAs; block-loaded b-frags) ----
#pragma unroll
    for (int dt = 0; dt < 8; ++dt) {
      const u32* vb_ = VpS + VROW * (8 * dt + g) + vxor;
      uint4 a4 = *reinterpret_cast<const uint4*>(vb_ + 0);
      uint4 b4 = *reinterpret_cast<const uint4*>(vb_ + 4);
      u32 vw[8] = {a4.x, a4.y, a4.z, a4.w, b4.x, b4.y, b4.z, b4.w};
#pragma unroll
      for (int u = 0; u < 4; ++u)
        mma_f16(O[dt][0], O[dt][1], O[dt][2], O[dt][3],
                h2lo[2 * u], h2hi[2 * u], h2lo[2 * u + 1], h2hi[2 * u + 1],
                vw[2 * u], vw[2 * u + 1]);
    }
    __syncthreads();  // before next tile's smem stores
  }

  // ---- epilogue: normalize and store ----
  const float inv0 = 1.f / l0, inv1 = 1.f / l1;
  float* Ow = Og + (bh * Sc + q0 + 16 * w) * (size_t)Dc;
#pragma unroll
  for (int dt = 0; dt < 8; ++dt) {
    int c = 8 * dt + 2 * tq;
    *reinterpret_cast<float2*>(Ow + (size_t)g * Dc + c) =
        make_float2(O[dt][0] * inv0, O[dt][1] * inv0);
    *reinterpret_cast<float2*>(Ow + (size_t)(g + 8) * Dc + c) =
        make_float2(O[dt][2] * inv1, O[dt][3] * inv1);
  }
}

}  // namespace

extern "C" void kernel_launch(void* const* d_in, const int* in_sizes, int n_in,
                              void* d_out, int out_size) {
  const float* Q = (const float*)d_in[0];
  const float* K = (const float*)d_in[1];
  const float* V = (const float*)d_in[2];
  float* O = (float*)d_out;
  (void)in_sizes; (void)n_in; (void)out_size;

  constexpr int B = 4, H = 16;
  dim3 grid(Sc / BM, B * H);
  fa_fwd<<<grid, NT>>>(Q, K, V, O);
}